// round 12
// baseline (speedup 1.0000x reference)
#include <cuda_runtime.h>
#include <cuda_fp16.h>
#include <cstdint>

static constexpr int BATCH = 65536;
static constexpr int KD    = 512;
static constexpr int ND    = 512;

static constexpr int BM = 128;
static constexpr int BN = 128;
static constexpr int BK = 64;          // 64 fp16 = 128B rows
static constexpr int NKITER = KD / BK; // 8
static constexpr int STAGES = 3;
static constexpr int TILE_BYTES = BM * 128;             // 16 KB
static constexpr int STAGE_BYTES = 2 * TILE_BYTES;      // 32 KB
static constexpr int SMEM_TOTAL = STAGES * STAGE_BYTES; // 96 KB -> 2 CTAs/SM

static constexpr int NBM = BATCH / BM;        // 512 row-blocks
static constexpr int WAVE_BM = 74;            // 296 resident CTAs / 4 bn

// ---------------- scratch + flags (no allocs allowed) ----------------
__device__ __align__(256) __half g_xh[(size_t)BATCH * KD];
__device__ __align__(256) __half g_wh[ND * KD];
__device__ int g_xflag[NBM];                  // counts 4 slice arrivals

// ---------------- helpers ----------------
static __device__ __forceinline__ uint32_t smem_u32(const void* p) {
    uint32_t a;
    asm("{ .reg .u64 t; cvta.to.shared.u64 t, %1; cvt.u32.u64 %0, t; }"
        : "=r"(a) : "l"(p));
    return a;
}

__device__ __forceinline__ void cp16(uint32_t dst, const void* src) {
    asm volatile("cp.async.cg.shared.global [%0], [%1], 16;"
                 :: "r"(dst), "l"(src) : "memory");
}
__device__ __forceinline__ void cp_commit() {
    asm volatile("cp.async.commit_group;" ::: "memory");
}
template <int N>
__device__ __forceinline__ void cp_wait() {
    asm volatile("cp.async.wait_group %0;" :: "n"(N) : "memory");
}

__device__ __forceinline__ void ldsm4(uint32_t& r0, uint32_t& r1, uint32_t& r2,
                                      uint32_t& r3, uint32_t addr) {
    asm volatile("ldmatrix.sync.aligned.m8n8.x4.shared.b16 {%0,%1,%2,%3}, [%4];"
                 : "=r"(r0), "=r"(r1), "=r"(r2), "=r"(r3) : "r"(addr));
}

// fp16-accumulate mma: D(fp16x4 in 2 regs) = A*B + D
__device__ __forceinline__ void mma16816h(uint32_t* d, const uint32_t* a, const uint32_t* b) {
    asm volatile(
        "mma.sync.aligned.m16n8k16.row.col.f16.f16.f16.f16 "
        "{%0,%1}, {%2,%3,%4,%5}, {%6,%7}, {%0,%1};"
        : "+r"(d[0]), "+r"(d[1])
        : "r"(a[0]), "r"(a[1]), "r"(a[2]), "r"(a[3]), "r"(b[0]), "r"(b[1]));
}

// ---------------- W prepass (row-major fp16) + flag clear ----------------
__global__ void __launch_bounds__(256) cvt_w_kernel(const float* __restrict__ s) {
    if (blockIdx.x == 0) {
        g_xflag[threadIdx.x] = 0;
        g_xflag[threadIdx.x + 256] = 0;
    }
    size_t idx = (size_t)blockIdx.x * 256 + threadIdx.x;  // one float4 each
    float4 v = reinterpret_cast<const float4*>(s)[idx];
    __half2 h0 = __floats2half2_rn(v.x, v.y);
    __half2 h1 = __floats2half2_rn(v.z, v.w);
    uint2 u;
    u.x = *reinterpret_cast<uint32_t*>(&h0);
    u.y = *reinterpret_cast<uint32_t*>(&h1);
    reinterpret_cast<uint2*>(g_wh)[idx] = u;
}

// convert one 32-row slice of a 128-row x block (256 threads, 16 float4 each)
__device__ __forceinline__ void convert_slice(const float* __restrict__ X,
                                              int blk, int slice, int tid) {
    const size_t base = ((size_t)blk * BM + (size_t)slice * 32) * KD;
    const float4* src = reinterpret_cast<const float4*>(X + base);
    uint2* dst = reinterpret_cast<uint2*>(g_xh + base);
#pragma unroll 4
    for (int i = 0; i < 16; i++) {
        int idx = tid + i * 256;
        float4 v = src[idx];
        __half2 h0 = __floats2half2_rn(v.x, v.y);
        __half2 h1 = __floats2half2_rn(v.z, v.w);
        uint2 u;
        u.x = *reinterpret_cast<uint32_t*>(&h0);
        u.y = *reinterpret_cast<uint32_t*>(&h1);
        dst[idx] = u;
    }
    __threadfence();
}

__device__ __forceinline__ void slice_arrive(int blk, int tid) {
    __syncthreads();
    if (tid == 0) atomicAdd(&g_xflag[blk], 1);
}

// ---------------- GEMM: fp16 window accumulation, promoted to fp32 every 2 kt ----------
// smem tile: 128 rows x 128B; 16B chunk c (0..7) of row r at r*128 + ((c ^ (r&7))<<4)
__global__ void __launch_bounds__(256, 2)
gemm_f16_kernel(const float* __restrict__ X, const float* __restrict__ Bv,
                float* __restrict__ Y) {
    extern __shared__ __align__(1024) char smem[];
    const uint32_t sb = smem_u32(smem);

    const int tid  = threadIdx.x;
    const int wid  = tid >> 5;
    const int lane = tid & 31;

    const int bm = blockIdx.x >> 2;
    const int bn = blockIdx.x & 3;
    const int row0 = bm * BM;
    const int col0 = bn * BN;

    if (bm < WAVE_BM) {
        convert_slice(X, bm, bn, tid);
        slice_arrive(bm, tid);
    }
    if (tid == 0) {
        while (atomicAdd(&g_xflag[bm], 0) != 4) { __nanosleep(200); }
    }
    __syncthreads();

    const int sr = tid >> 3;
    const int sc = tid & 7;
    const uint32_t sdst = (uint32_t)(sr * 128 + (((uint32_t)sc ^ (uint32_t)(sr & 7)) << 4));
    const __half* Asrc0 = g_xh + (size_t)(row0 + sr) * KD + sc * 8;
    const __half* Bsrc0 = g_wh + (size_t)(col0 + sr) * KD + sc * 8;

    auto stage = [&](int kt, int slot) {
        const uint32_t base = sb + slot * STAGE_BYTES + sdst;
        const __half* as = Asrc0 + kt * BK;
        const __half* bs = Bsrc0 + kt * BK;
#pragma unroll
        for (int i = 0; i < 4; i++)
            cp16(base + i * (32 * 128), as + (size_t)(32 * i) * KD);
#pragma unroll
        for (int i = 0; i < 4; i++)
            cp16(base + TILE_BYTES + i * (32 * 128), bs + (size_t)(32 * i) * KD);
    };

    stage(0, 0); cp_commit();
    stage(1, 1); cp_commit();

    if (bm + WAVE_BM < NBM) {
        convert_slice(X, bm + WAVE_BM, bn, tid);
        slice_arrive(bm + WAVE_BM, tid);
    }

    const int wm = wid & 1;
    const int wn = wid >> 1;
    const uint32_t sw  = (uint32_t)((lane & 7) << 4);
    const uint32_t c16 = (uint32_t)((lane >> 4) << 4);
    uint32_t aRow[4], bRow[2], kx[4];
#pragma unroll
    for (int mt = 0; mt < 4; mt++)
        aRow[mt] = (uint32_t)((wm * 64 + mt * 16 + (lane & 15)) * 128);
#pragma unroll
    for (int np = 0; np < 2; np++)
        bRow[np] = (uint32_t)((wn * 32 + np * 16 + (lane & 15)) * 128);
#pragma unroll
    for (int ks = 0; ks < 4; ks++)
        kx[ks] = (uint32_t)(ks * 32 + c16) ^ sw;

    float acc[4][4][4];
    uint32_t hacc[4][4][2];
#pragma unroll
    for (int i = 0; i < 4; i++)
#pragma unroll
        for (int j = 0; j < 4; j++) {
#pragma unroll
            for (int e = 0; e < 4; e++) acc[i][j][e] = 0.0f;
            hacc[i][j][0] = 0u; hacc[i][j][1] = 0u;
        }

    for (int kt = 0; kt < NKITER; kt++) {
        cp_wait<1>();
        __syncthreads();
        if (kt + 2 < NKITER) stage(kt + 2, (kt + 2) % STAGES);
        cp_commit();

        const uint32_t abase = sb + (kt % STAGES) * STAGE_BYTES;
        const uint32_t bbase = abase + TILE_BYTES;
#pragma unroll
        for (int ks = 0; ks < 4; ks++) {
            uint32_t af[4][4], bf[2][4];
#pragma unroll
            for (int mt = 0; mt < 4; mt++)
                ldsm4(af[mt][0], af[mt][1], af[mt][2], af[mt][3],
                      abase + aRow[mt] + kx[ks]);
#pragma unroll
            for (int np = 0; np < 2; np++)
                ldsm4(bf[np][0], bf[np][1], bf[np][2], bf[np][3],
                      bbase + bRow[np] + kx[ks]);
#pragma unroll
            for (int mt = 0; mt < 4; mt++) {
#pragma unroll
                for (int nt = 0; nt < 4; nt++) {
                    uint32_t bb[2] = { bf[nt >> 1][(nt & 1)],
                                       bf[nt >> 1][(nt & 1) + 2] };
                    mma16816h(hacc[mt][nt], af[mt], bb);
                }
            }
        }

        // promote fp16 window accumulators into fp32 every 2 kt (K window = 128)
        if ((kt & 1) == 1) {
#pragma unroll
            for (int mt = 0; mt < 4; mt++) {
#pragma unroll
                for (int nt = 0; nt < 4; nt++) {
                    float2 f0 = __half22float2(*reinterpret_cast<__half2*>(&hacc[mt][nt][0]));
                    float2 f1 = __half22float2(*reinterpret_cast<__half2*>(&hacc[mt][nt][1]));
                    acc[mt][nt][0] += f0.x;
                    acc[mt][nt][1] += f0.y;
                    acc[mt][nt][2] += f1.x;
                    acc[mt][nt][3] += f1.y;
                    hacc[mt][nt][0] = 0u;
                    hacc[mt][nt][1] = 0u;
                }
            }
        }
    }

    // epilogue: bias + fp32 store
    const int crow = row0 + wm * 64;
    const int ccol = col0 + wn * 32;
#pragma unroll
    for (int nt = 0; nt < 4; nt++) {
        const int c = ccol + nt * 8 + (lane & 3) * 2;
        const float2 bv = *reinterpret_cast<const float2*>(Bv + c);
#pragma unroll
        for (int mt = 0; mt < 4; mt++) {
            const int r = crow + mt * 16 + (lane >> 2);
            float2 v0, v1;
            v0.x = acc[mt][nt][0] + bv.x;
            v0.y = acc[mt][nt][1] + bv.y;
            v1.x = acc[mt][nt][2] + bv.x;
            v1.y = acc[mt][nt][3] + bv.y;
            *reinterpret_cast<float2*>(Y + (size_t)r * ND + c) = v0;
            *reinterpret_cast<float2*>(Y + (size_t)(r + 8) * ND + c) = v1;
        }
    }
}

extern "C" void kernel_launch(void* const* d_in, const int* in_sizes, int n_in,
                              void* d_out, int out_size) {
    const float* x = nullptr;
    const float* w = nullptr;
    const float* b = nullptr;
    for (int i = 0; i < n_in; i++) {
        if (in_sizes[i] == BATCH * KD)   x = (const float*)d_in[i];
        else if (in_sizes[i] == ND * KD) w = (const float*)d_in[i];
        else if (in_sizes[i] == ND)      b = (const float*)d_in[i];
    }
    float* out = (float*)d_out;

    cvt_w_kernel<<<(ND * KD / 4) / 256, 256>>>(w);   // ~1 us, also clears flags

    cudaFuncSetAttribute(gemm_f16_kernel,
                         cudaFuncAttributeMaxDynamicSharedMemorySize, SMEM_TOTAL);
    gemm_f16_kernel<<<(BATCH / BM) * (ND / BN), 256, SMEM_TOTAL>>>(x, b, out);
}

// round 13
// speedup vs baseline: 1.1085x; 1.1085x over previous
#include <cuda_runtime.h>
#include <cuda_fp16.h>
#include <cstdint>

static constexpr int BATCH = 65536;
static constexpr int KD    = 512;
static constexpr int ND    = 512;

static constexpr int BM = 128;
static constexpr int BN = 128;
static constexpr int BK = 64;          // 64 fp16 = 128B rows
static constexpr int NKITER = KD / BK; // 8
static constexpr int STAGES = 3;
static constexpr int TILE_BYTES = BM * 128;             // 16 KB
static constexpr int STAGE_BYTES = 2 * TILE_BYTES;      // 32 KB
static constexpr int SMEM_TOTAL = STAGES * STAGE_BYTES; // 96 KB -> 2 CTAs/SM

static constexpr int NBM = BATCH / BM;        // 512 row-blocks
static constexpr int WAVE_BM = 74;            // 296 resident CTAs / 4 bn

// ---------------- scratch + flags (no allocs allowed) ----------------
__device__ __align__(256) __half g_xh[(size_t)BATCH * KD];
__device__ __align__(256) __half g_wh[ND * KD];
__device__ int g_xflag[NBM];                  // counts 4 slice arrivals

// ---------------- helpers ----------------
static __device__ __forceinline__ uint32_t smem_u32(const void* p) {
    uint32_t a;
    asm("{ .reg .u64 t; cvta.to.shared.u64 t, %1; cvt.u32.u64 %0, t; }"
        : "=r"(a) : "l"(p));
    return a;
}

__device__ __forceinline__ void cp16(uint32_t dst, const void* src) {
    asm volatile("cp.async.cg.shared.global [%0], [%1], 16;"
                 :: "r"(dst), "l"(src) : "memory");
}
__device__ __forceinline__ void cp_commit() {
    asm volatile("cp.async.commit_group;" ::: "memory");
}
template <int N>
__device__ __forceinline__ void cp_wait() {
    asm volatile("cp.async.wait_group %0;" :: "n"(N) : "memory");
}

__device__ __forceinline__ void ldsm4(uint32_t& r0, uint32_t& r1, uint32_t& r2,
                                      uint32_t& r3, uint32_t addr) {
    asm volatile("ldmatrix.sync.aligned.m8n8.x4.shared.b16 {%0,%1,%2,%3}, [%4];"
                 : "=r"(r0), "=r"(r1), "=r"(r2), "=r"(r3) : "r"(addr));
}

__device__ __forceinline__ void mma16816(float* d, const uint32_t* a, const uint32_t* b) {
    asm volatile(
        "mma.sync.aligned.m16n8k16.row.col.f32.f16.f16.f32 "
        "{%0,%1,%2,%3}, {%4,%5,%6,%7}, {%8,%9}, {%0,%1,%2,%3};"
        : "+f"(d[0]), "+f"(d[1]), "+f"(d[2]), "+f"(d[3])
        : "r"(a[0]), "r"(a[1]), "r"(a[2]), "r"(a[3]), "r"(b[0]), "r"(b[1]));
}

// ---------------- W prepass (row-major fp16) + flag clear ----------------
__global__ void __launch_bounds__(256) cvt_w_kernel(const float* __restrict__ s) {
    if (blockIdx.x == 0) {
        g_xflag[threadIdx.x] = 0;
        g_xflag[threadIdx.x + 256] = 0;
    }
    size_t idx = (size_t)blockIdx.x * 256 + threadIdx.x;  // one float4 each
    float4 v = reinterpret_cast<const float4*>(s)[idx];
    __half2 h0 = __floats2half2_rn(v.x, v.y);
    __half2 h1 = __floats2half2_rn(v.z, v.w);
    uint2 u;
    u.x = *reinterpret_cast<uint32_t*>(&h0);
    u.y = *reinterpret_cast<uint32_t*>(&h1);
    reinterpret_cast<uint2*>(g_wh)[idx] = u;
}

// convert one 32-row slice of a 128-row x block (256 threads, 16 float4 each)
__device__ __forceinline__ void convert_slice(const float* __restrict__ X,
                                              int blk, int slice, int tid) {
    const size_t base = ((size_t)blk * BM + (size_t)slice * 32) * KD;
    const float4* src = reinterpret_cast<const float4*>(X + base);
    uint2* dst = reinterpret_cast<uint2*>(g_xh + base);
#pragma unroll 4
    for (int i = 0; i < 16; i++) {
        int idx = tid + i * 256;
        float4 v = src[idx];
        __half2 h0 = __floats2half2_rn(v.x, v.y);
        __half2 h1 = __floats2half2_rn(v.z, v.w);
        uint2 u;
        u.x = *reinterpret_cast<uint32_t*>(&h0);
        u.y = *reinterpret_cast<uint32_t*>(&h1);
        dst[idx] = u;
    }
    __threadfence();
}

__device__ __forceinline__ void slice_arrive(int blk, int tid) {
    __syncthreads();
    if (tid == 0) atomicAdd(&g_xflag[blk], 1);
}

// ---------------- GEMM with balanced pipelined conversion + split prologue ----------
// smem tile: 128 rows x 128B; 16B chunk c (0..7) of row r at r*128 + ((c ^ (r&7))<<4)
__global__ void __launch_bounds__(256, 2)
gemm_f16_kernel(const float* __restrict__ X, const float* __restrict__ Bv,
                float* __restrict__ Y) {
    extern __shared__ __align__(1024) char smem[];
    const uint32_t sb = smem_u32(smem);

    const int tid  = threadIdx.x;
    const int wid  = tid >> 5;
    const int lane = tid & 31;

    const int bm = blockIdx.x >> 2;
    const int bn = blockIdx.x & 3;
    const int row0 = bm * BM;
    const int col0 = bn * BN;

    // staging geometry
    const int sr = tid >> 3;
    const int sc = tid & 7;
    const uint32_t sdst = (uint32_t)(sr * 128 + (((uint32_t)sc ^ (uint32_t)(sr & 7)) << 4));
    const __half* Asrc0 = g_xh + (size_t)(row0 + sr) * KD + sc * 8;
    const __half* Bsrc0 = g_wh + (size_t)(col0 + sr) * KD + sc * 8;

    auto stageA = [&](int kt, int slot) {
        const uint32_t base = sb + slot * STAGE_BYTES + sdst;
        const __half* as = Asrc0 + kt * BK;
#pragma unroll
        for (int i = 0; i < 4; i++)
            cp16(base + i * (32 * 128), as + (size_t)(32 * i) * KD);
    };
    auto stageB = [&](int kt, int slot) {
        const uint32_t base = sb + slot * STAGE_BYTES + sdst + TILE_BYTES;
        const __half* bs = Bsrc0 + kt * BK;
#pragma unroll
        for (int i = 0; i < 4; i++)
            cp16(base + i * (32 * 128), bs + (size_t)(32 * i) * KD);
    };
    auto stage = [&](int kt, int slot) { stageA(kt, slot); stageB(kt, slot); };

    // B staging does not depend on x: issue it before the x-flag wait.
    stageB(0, 0); cp_commit();
    stageB(1, 1); cp_commit();

    // wave-0: every CTA converts slice bn of its OWN block (overlaps B staging)
    if (bm < WAVE_BM) {
        convert_slice(X, bm, bn, tid);
        slice_arrive(bm, tid);
    }
    // wait for own block fully converted (4 slices)
    if (tid == 0) {
        while (atomicAdd(&g_xflag[bm], 0) != 4) { __nanosleep(200); }
    }
    __syncthreads();

    // now A tiles (groups retire in order: B0, B1, A0, A1)
    stageA(0, 0); cp_commit();
    stageA(1, 1); cp_commit();

    // converter duty: slice bn of NEXT wave's block, overlapped with cp.async
    if (bm + WAVE_BM < NBM) {
        convert_slice(X, bm + WAVE_BM, bn, tid);
        slice_arrive(bm + WAVE_BM, tid);
    }

    // fragment addressing: warp tile 64x32, 2x4 warp grid
    const int wm = wid & 1;
    const int wn = wid >> 1;
    const uint32_t sw  = (uint32_t)((lane & 7) << 4);
    const uint32_t c16 = (uint32_t)((lane >> 4) << 4);
    uint32_t aRow[4], bRow[2], kx[4];
#pragma unroll
    for (int mt = 0; mt < 4; mt++)
        aRow[mt] = (uint32_t)((wm * 64 + mt * 16 + (lane & 15)) * 128);
#pragma unroll
    for (int np = 0; np < 2; np++)
        bRow[np] = (uint32_t)((wn * 32 + np * 16 + (lane & 15)) * 128);
#pragma unroll
    for (int ks = 0; ks < 4; ks++)
        kx[ks] = (uint32_t)(ks * 32 + c16) ^ sw;

    float acc[4][4][4];
#pragma unroll
    for (int i = 0; i < 4; i++)
#pragma unroll
        for (int j = 0; j < 4; j++)
#pragma unroll
            for (int e = 0; e < 4; e++) acc[i][j][e] = 0.0f;

    for (int kt = 0; kt < NKITER; kt++) {
        // kt=0: pending [B0,B1,A0,A1] -> <=1 leaves A1 only (B0,B1,A0 done).
        // kt=1: pending [A1,S2] -> <=1 leaves S2. Steady state thereafter.
        cp_wait<1>();
        __syncthreads();
        if (kt + 2 < NKITER) stage(kt + 2, (kt + 2) % STAGES);
        cp_commit();

        const uint32_t abase = sb + (kt % STAGES) * STAGE_BYTES;
        const uint32_t bbase = abase + TILE_BYTES;
#pragma unroll
        for (int ks = 0; ks < 4; ks++) {
            uint32_t af[4][4], bf[2][4];
#pragma unroll
            for (int mt = 0; mt < 4; mt++)
                ldsm4(af[mt][0], af[mt][1], af[mt][2], af[mt][3],
                      abase + aRow[mt] + kx[ks]);
#pragma unroll
            for (int np = 0; np < 2; np++)
                ldsm4(bf[np][0], bf[np][1], bf[np][2], bf[np][3],
                      bbase + bRow[np] + kx[ks]);
#pragma unroll
            for (int mt = 0; mt < 4; mt++) {
#pragma unroll
                for (int nt = 0; nt < 4; nt++) {
                    uint32_t bb[2] = { bf[nt >> 1][(nt & 1)],
                                       bf[nt >> 1][(nt & 1) + 2] };
                    mma16816(acc[mt][nt], af[mt], bb);
                }
            }
        }
    }

    // epilogue: bias + fp32 store
    const int crow = row0 + wm * 64;
    const int ccol = col0 + wn * 32;
#pragma unroll
    for (int nt = 0; nt < 4; nt++) {
        const int c = ccol + nt * 8 + (lane & 3) * 2;
        const float2 bv = *reinterpret_cast<const float2*>(Bv + c);
#pragma unroll
        for (int mt = 0; mt < 4; mt++) {
            const int r = crow + mt * 16 + (lane >> 2);
            float2 v0, v1;
            v0.x = acc[mt][nt][0] + bv.x;
            v0.y = acc[mt][nt][1] + bv.y;
            v1.x = acc[mt][nt][2] + bv.x;
            v1.y = acc[mt][nt][3] + bv.y;
            *reinterpret_cast<float2*>(Y + (size_t)r * ND + c) = v0;
            *reinterpret_cast<float2*>(Y + (size_t)(r + 8) * ND + c) = v1;
        }
    }
}

extern "C" void kernel_launch(void* const* d_in, const int* in_sizes, int n_in,
                              void* d_out, int out_size) {
    const float* x = nullptr;
    const float* w = nullptr;
    const float* b = nullptr;
    for (int i = 0; i < n_in; i++) {
        if (in_sizes[i] == BATCH * KD)   x = (const float*)d_in[i];
        else if (in_sizes[i] == ND * KD) w = (const float*)d_in[i];
        else if (in_sizes[i] == ND)      b = (const float*)d_in[i];
    }
    float* out = (float*)d_out;

    cvt_w_kernel<<<(ND * KD / 4) / 256, 256>>>(w);   // ~1 us, also clears flags

    cudaFuncSetAttribute(gemm_f16_kernel,
                         cudaFuncAttributeMaxDynamicSharedMemorySize, SMEM_TOTAL);
    gemm_f16_kernel<<<(BATCH / BM) * (ND / BN), 256, SMEM_TOTAL>>>(x, b, out);
}